// round 1
// baseline (speedup 1.0000x reference)
#include <cuda_runtime.h>
#include <math.h>

#define BB 16
#define TT 2048
#define DD 1024
#define HH 128
#define BT (BB*TT)

// Scratch (allocation-free rule: __device__ globals)
__device__ float g_q[(size_t)BT*HH];   // pre-scaled by H^-0.5
__device__ float g_k[(size_t)BT*HH];
__device__ float g_v[(size_t)BT*HH];
__device__ float g_colsum[BT];         // per (b,k): sum_{q>=k} exp(S[q,k])

// ---------------------------------------------------------------------------
// K1: projection GEMM  out[row, n] = (x[row,:] @ W[:,n] + b[n]) * sc
// rows = 32768, inner = 1024, cols = 128. Tile 128x128, BK=16, 256 thr, 8x8.
// ---------------------------------------------------------------------------
__global__ __launch_bounds__(256) void proj_kernel(const float* __restrict__ x,
                                                   const float* __restrict__ W,
                                                   const float* __restrict__ bias,
                                                   int sel)
{
    __shared__ float As[16][132];
    __shared__ float Bs[16][128];
    const int tid = threadIdx.x;
    const int tm = tid >> 4;
    const int tn = tid & 15;
    const int row0 = blockIdx.x * 128;

    const int lm = tid >> 1;            // A-load row 0..127
    const int lk = (tid & 1) * 8;       // A-load k offset
    const float* xr = x + (size_t)(row0 + lm) * DD + lk;
    const int wk = tid >> 4;            // B-load k row 0..15
    const int wn = (tid & 15) * 8;      // B-load col

    float acc[8][8];
    #pragma unroll
    for (int i = 0; i < 8; i++)
        #pragma unroll
        for (int j = 0; j < 8; j++) acc[i][j] = 0.f;

    for (int k0 = 0; k0 < DD; k0 += 16) {
        float4 a0 = *(const float4*)(xr + k0);
        float4 a1 = *(const float4*)(xr + k0 + 4);
        float4 b0 = *(const float4*)(W + (size_t)(k0 + wk) * HH + wn);
        float4 b1 = *(const float4*)(W + (size_t)(k0 + wk) * HH + wn + 4);

        As[lk+0][lm] = a0.x; As[lk+1][lm] = a0.y; As[lk+2][lm] = a0.z; As[lk+3][lm] = a0.w;
        As[lk+4][lm] = a1.x; As[lk+5][lm] = a1.y; As[lk+6][lm] = a1.z; As[lk+7][lm] = a1.w;
        *(float4*)&Bs[wk][wn]   = b0;
        *(float4*)&Bs[wk][wn+4] = b1;
        __syncthreads();

        #pragma unroll
        for (int kk = 0; kk < 16; kk++) {
            float a[8], bb[8];
            *(float4*)(a)    = *(const float4*)&As[kk][tm*8];
            *(float4*)(a+4)  = *(const float4*)&As[kk][tm*8+4];
            *(float4*)(bb)   = *(const float4*)&Bs[kk][tn*8];
            *(float4*)(bb+4) = *(const float4*)&Bs[kk][tn*8+4];
            #pragma unroll
            for (int i = 0; i < 8; i++)
                #pragma unroll
                for (int j = 0; j < 8; j++)
                    acc[i][j] = fmaf(a[i], bb[j], acc[i][j]);
        }
        __syncthreads();
    }

    float* dst = (sel == 0) ? g_q : (sel == 1) ? g_k : g_v;
    const float sc = (sel == 0) ? 0.08838834764831845f : 1.0f;  // H^-0.5 folded into q

    float bj[8];
    *(float4*)(bj)   = *(const float4*)(bias + tn*8);
    *(float4*)(bj+4) = *(const float4*)(bias + tn*8 + 4);

    #pragma unroll
    for (int i = 0; i < 8; i++) {
        float4 o0, o1;
        o0.x = (acc[i][0] + bj[0]) * sc;
        o0.y = (acc[i][1] + bj[1]) * sc;
        o0.z = (acc[i][2] + bj[2]) * sc;
        o0.w = (acc[i][3] + bj[3]) * sc;
        o1.x = (acc[i][4] + bj[4]) * sc;
        o1.y = (acc[i][5] + bj[5]) * sc;
        o1.z = (acc[i][6] + bj[6]) * sc;
        o1.w = (acc[i][7] + bj[7]) * sc;
        size_t off = (size_t)(row0 + tm*8 + i) * HH + tn*8;
        *(float4*)(dst + off)     = o0;
        *(float4*)(dst + off + 4) = o1;
    }
}

// ---------------------------------------------------------------------------
// zero colsum
// ---------------------------------------------------------------------------
__global__ void zero_kernel()
{
    int i = blockIdx.x * blockDim.x + threadIdx.x;
    if (i < BT) g_colsum[i] = 0.f;
}

// ---------------------------------------------------------------------------
// K2: column stats. S tile 128(q) x 128(k); exp only where q>=k; column sums
// atomically accumulated into g_colsum. grid = (kt, qt, b), skip qt < kt.
// ---------------------------------------------------------------------------
__global__ __launch_bounds__(256) void colsum_kernel()
{
    const int kt = blockIdx.x, qt = blockIdx.y, b = blockIdx.z;
    if (qt < kt) return;

    __shared__ float Qs[32][132];
    __shared__ float Ks[32][132];
    __shared__ float red[16][128];

    const int tid = threadIdx.x;
    const int tm = tid >> 4;
    const int tn = tid & 15;
    const int q0 = qt * 128, k0 = kt * 128;

    const float* Qg = g_q + ((size_t)b*TT + q0) * HH;
    const float* Kg = g_k + ((size_t)b*TT + k0) * HH;

    float acc[8][8];
    #pragma unroll
    for (int i = 0; i < 8; i++)
        #pragma unroll
        for (int j = 0; j < 8; j++) acc[i][j] = 0.f;

    const int lm = tid >> 1;           // 0..127
    const int lh = (tid & 1) * 16;     // 0 or 16

    for (int h0 = 0; h0 < HH; h0 += 32) {
        const float* qr = Qg + (size_t)lm * HH + h0 + lh;
        const float* kr = Kg + (size_t)lm * HH + h0 + lh;
        float4 qv0 = *(const float4*)(qr);
        float4 qv1 = *(const float4*)(qr + 4);
        float4 qv2 = *(const float4*)(qr + 8);
        float4 qv3 = *(const float4*)(qr + 12);
        float4 kv0 = *(const float4*)(kr);
        float4 kv1 = *(const float4*)(kr + 4);
        float4 kv2 = *(const float4*)(kr + 8);
        float4 kv3 = *(const float4*)(kr + 12);
        __syncthreads();
        Qs[lh+ 0][lm]=qv0.x; Qs[lh+ 1][lm]=qv0.y; Qs[lh+ 2][lm]=qv0.z; Qs[lh+ 3][lm]=qv0.w;
        Qs[lh+ 4][lm]=qv1.x; Qs[lh+ 5][lm]=qv1.y; Qs[lh+ 6][lm]=qv1.z; Qs[lh+ 7][lm]=qv1.w;
        Qs[lh+ 8][lm]=qv2.x; Qs[lh+ 9][lm]=qv2.y; Qs[lh+10][lm]=qv2.z; Qs[lh+11][lm]=qv2.w;
        Qs[lh+12][lm]=qv3.x; Qs[lh+13][lm]=qv3.y; Qs[lh+14][lm]=qv3.z; Qs[lh+15][lm]=qv3.w;
        Ks[lh+ 0][lm]=kv0.x; Ks[lh+ 1][lm]=kv0.y; Ks[lh+ 2][lm]=kv0.z; Ks[lh+ 3][lm]=kv0.w;
        Ks[lh+ 4][lm]=kv1.x; Ks[lh+ 5][lm]=kv1.y; Ks[lh+ 6][lm]=kv1.z; Ks[lh+ 7][lm]=kv1.w;
        Ks[lh+ 8][lm]=kv2.x; Ks[lh+ 9][lm]=kv2.y; Ks[lh+10][lm]=kv2.z; Ks[lh+11][lm]=kv2.w;
        Ks[lh+12][lm]=kv3.x; Ks[lh+13][lm]=kv3.y; Ks[lh+14][lm]=kv3.z; Ks[lh+15][lm]=kv3.w;
        __syncthreads();

        #pragma unroll 4
        for (int hh = 0; hh < 32; hh++) {
            float a[8], bb[8];
            *(float4*)(a)    = *(const float4*)&Qs[hh][tm*8];
            *(float4*)(a+4)  = *(const float4*)&Qs[hh][tm*8+4];
            *(float4*)(bb)   = *(const float4*)&Ks[hh][tn*8];
            *(float4*)(bb+4) = *(const float4*)&Ks[hh][tn*8+4];
            #pragma unroll
            for (int i = 0; i < 8; i++)
                #pragma unroll
                for (int j = 0; j < 8; j++)
                    acc[i][j] = fmaf(a[i], bb[j], acc[i][j]);
        }
    }

    // mask + exp + per-thread column partials
    float cp[8];
    #pragma unroll
    for (int j = 0; j < 8; j++) {
        const int k = k0 + tn*8 + j;
        float s = 0.f;
        #pragma unroll
        for (int i = 0; i < 8; i++) {
            const int q = q0 + tm*8 + i;
            if (q >= k) s += __expf(acc[i][j]);
        }
        cp[j] = s;
    }
    __syncthreads();
    #pragma unroll
    for (int j = 0; j < 8; j++) red[tm][tn*8 + j] = cp[j];
    __syncthreads();
    if (tid < 128) {
        float s = 0.f;
        #pragma unroll
        for (int r = 0; r < 16; r++) s += red[r][tid];
        atomicAdd(&g_colsum[(size_t)b*TT + k0 + tid], s);
    }
}

// ---------------------------------------------------------------------------
// K3: output pass. Block = 128 q rows x full H. Q tile resident in smem,
// loop k chunks of 64: S = Q·K^T, P = mask·exp·(1/colsum), O += P·V.
// ---------------------------------------------------------------------------
#define QS_LD 132
#define KS_LD 68
#define VS_LD 132
#define PS_LD 68
#define SMEM_F (128*QS_LD + 128*KS_LD + 64*VS_LD + 128*PS_LD + 64)
#define SMEM_BYTES (SMEM_F * 4)

__global__ __launch_bounds__(256) void out_kernel(float* __restrict__ out)
{
    extern __shared__ float sm[];
    float* Qs  = sm;                       // [h][q]  128 x QS_LD
    float* Ks  = Qs + 128*QS_LD;           // [h][kk] 128 x KS_LD
    float* Vs  = Ks + 128*KS_LD;           // [kk][h]  64 x VS_LD
    float* Ps  = Vs + 64*VS_LD;            // [q][kk] 128 x PS_LD
    float* inv = Ps + 128*PS_LD;           // [64]

    const int qt = blockIdx.x, b = blockIdx.y;
    const int q0 = qt * 128;
    const int tid = threadIdx.x;
    const int tm = tid >> 4;
    const int tn = tid & 15;

    // Load Q tile transposed into smem (once)
    {
        const int m = tid >> 1, hoff = (tid & 1) * 64;
        const float* qr = g_q + ((size_t)b*TT + q0 + m) * HH + hoff;
        #pragma unroll
        for (int u = 0; u < 64; u += 4) {
            float4 v = *(const float4*)(qr + u);
            Qs[(hoff+u+0)*QS_LD + m] = v.x;
            Qs[(hoff+u+1)*QS_LD + m] = v.y;
            Qs[(hoff+u+2)*QS_LD + m] = v.z;
            Qs[(hoff+u+3)*QS_LD + m] = v.w;
        }
    }

    float acc[8][8];
    #pragma unroll
    for (int i = 0; i < 8; i++)
        #pragma unroll
        for (int j = 0; j < 8; j++) acc[i][j] = 0.f;

    const int nk = (qt + 1) * 128;   // k ranges [0, nk)
    for (int kc = 0; kc < nk; kc += 64) {
        __syncthreads();   // previous chunk fully consumed

        // K chunk: 64 rows x 128 h, stored transposed [h][kk]
        {
            const int kk = tid >> 2, hoff = (tid & 3) * 32;
            const float* kr = g_k + ((size_t)b*TT + kc + kk) * HH + hoff;
            #pragma unroll
            for (int u = 0; u < 32; u += 4) {
                float4 v = *(const float4*)(kr + u);
                Ks[(hoff+u+0)*KS_LD + kk] = v.x;
                Ks[(hoff+u+1)*KS_LD + kk] = v.y;
                Ks[(hoff+u+2)*KS_LD + kk] = v.z;
                Ks[(hoff+u+3)*KS_LD + kk] = v.w;
            }
        }
        // V chunk: natural layout [kk][h]
        {
            const int kk = tid >> 2, hoff = (tid & 3) * 32;
            const float* vr = g_v + ((size_t)b*TT + kc + kk) * HH + hoff;
            #pragma unroll
            for (int u = 0; u < 32; u += 4)
                *(float4*)&Vs[kk*VS_LD + hoff + u] = *(const float4*)(vr + u);
        }
        if (tid < 64) inv[tid] = 1.f / g_colsum[(size_t)b*TT + kc + tid];
        __syncthreads();

        // S sub-tile per thread: 8 q x 4 k
        float s[8][4];
        #pragma unroll
        for (int i = 0; i < 8; i++)
            #pragma unroll
            for (int j = 0; j < 4; j++) s[i][j] = 0.f;

        #pragma unroll 4
        for (int h = 0; h < 128; h++) {
            float a[8], bb[4];
            *(float4*)(a)   = *(const float4*)&Qs[h*QS_LD + tm*8];
            *(float4*)(a+4) = *(const float4*)&Qs[h*QS_LD + tm*8 + 4];
            *(float4*)(bb)  = *(const float4*)&Ks[h*KS_LD + tn*4];
            #pragma unroll
            for (int i = 0; i < 8; i++)
                #pragma unroll
                for (int j = 0; j < 4; j++)
                    s[i][j] = fmaf(a[i], bb[j], s[i][j]);
        }

        // mask + exp + normalize -> Ps
        #pragma unroll
        for (int i = 0; i < 8; i++) {
            const int q = q0 + tm*8 + i;
            float4 p;
            const int kb = kc + tn*4;
            p.x = (q >= kb+0) ? __expf(s[i][0]) * inv[tn*4+0] : 0.f;
            p.y = (q >= kb+1) ? __expf(s[i][1]) * inv[tn*4+1] : 0.f;
            p.z = (q >= kb+2) ? __expf(s[i][2]) * inv[tn*4+2] : 0.f;
            p.w = (q >= kb+3) ? __expf(s[i][3]) * inv[tn*4+3] : 0.f;
            *(float4*)&Ps[(tm*8+i)*PS_LD + tn*4] = p;
        }
        __syncthreads();

        // O += P (128x64) @ V (64x128); thread: 8 q x 8 h
        #pragma unroll 2
        for (int kk = 0; kk < 64; kk++) {
            float a[8], bb[8];
            #pragma unroll
            for (int i = 0; i < 8; i++) a[i] = Ps[(tm*8+i)*PS_LD + kk];
            *(float4*)(bb)   = *(const float4*)&Vs[kk*VS_LD + tn*8];
            *(float4*)(bb+4) = *(const float4*)&Vs[kk*VS_LD + tn*8 + 4];
            #pragma unroll
            for (int i = 0; i < 8; i++)
                #pragma unroll
                for (int j = 0; j < 8; j++)
                    acc[i][j] = fmaf(a[i], bb[j], acc[i][j]);
        }
    }

    // write O
    #pragma unroll
    for (int i = 0; i < 8; i++) {
        size_t off = ((size_t)b*TT + q0 + tm*8 + i) * HH + tn*8;
        float4 o0, o1;
        o0.x = acc[i][0]; o0.y = acc[i][1]; o0.z = acc[i][2]; o0.w = acc[i][3];
        o1.x = acc[i][4]; o1.y = acc[i][5]; o1.z = acc[i][6]; o1.w = acc[i][7];
        *(float4*)(out + off)     = o0;
        *(float4*)(out + off + 4) = o1;
    }
}

// ---------------------------------------------------------------------------
extern "C" void kernel_launch(void* const* d_in, const int* in_sizes, int n_in,
                              void* d_out, int out_size)
{
    const float* x  = (const float*)d_in[0];
    const float* Wk = (const float*)d_in[1];
    const float* bk = (const float*)d_in[2];
    const float* Wq = (const float*)d_in[3];
    const float* bq = (const float*)d_in[4];
    const float* Wv = (const float*)d_in[5];
    const float* bv = (const float*)d_in[6];
    float* out = (float*)d_out;

    cudaFuncSetAttribute(out_kernel, cudaFuncAttributeMaxDynamicSharedMemorySize, SMEM_BYTES);

    proj_kernel<<<BT/128, 256>>>(x, Wq, bq, 0);   // q (pre-scaled)
    proj_kernel<<<BT/128, 256>>>(x, Wk, bk, 1);   // k
    proj_kernel<<<BT/128, 256>>>(x, Wv, bv, 2);   // v
    zero_kernel<<<(BT + 255)/256, 256>>>();
    colsum_kernel<<<dim3(TT/128, TT/128, BB), 256>>>();
    out_kernel<<<dim3(TT/128, BB), 256, SMEM_BYTES>>>(out);
}

// round 3
// speedup vs baseline: 4.7787x; 4.7787x over previous
#include <cuda_runtime.h>
#include <cstdint>

#define BB 16
#define TT 2048
#define DD 1024
#define HH 128
#define BT (BB*TT)

// ---------------- device scratch (allocation-free rule) ----------------
__device__ __align__(128) float g_x[(size_t)BT*DD];       // tf32-rounded copy of x
__device__ __align__(128) float g_q[(size_t)BT*HH];       // tf32-rounded, pre-scaled
__device__ __align__(128) float g_k[(size_t)BT*HH];       // tf32-rounded
__device__ __align__(128) float g_v[(size_t)BT*HH];       // fp32 (rounded later in Vt)
__device__ __align__(128) float g_Wt[3*(size_t)HH*DD];    // [sel][n][k], tf32-rounded
__device__ __align__(128) float g_Vt[(size_t)BB*HH*TT];   // [b][h][k] = v/colsum, tf32-rounded
__device__ __align__(128) float g_colsum[BT];
__device__ __align__(128) float g_E[(size_t)BB*TT*TT];    // exp(masked S), tf32-rounded

// ---------------- helpers ----------------
__device__ __forceinline__ float rna(float x) {
    uint32_t u;
    asm("cvt.rna.tf32.f32 %0, %1;" : "=r"(u) : "f"(x));
    return __uint_as_float(u);
}
__device__ __forceinline__ uint32_t smem_u32(const void* p) {
    uint32_t a;
    asm("{ .reg .u64 t; cvta.to.shared.u64 t, %1; cvt.u32.u64 %0, t; }" : "=r"(a) : "l"(p));
    return a;
}
__device__ __forceinline__ void mma8(float* c, const uint32_t* a, const uint32_t* b) {
    asm volatile(
        "mma.sync.aligned.m16n8k8.row.col.f32.tf32.tf32.f32 "
        "{%0,%1,%2,%3}, {%4,%5,%6,%7}, {%8,%9}, {%0,%1,%2,%3};"
        : "+f"(c[0]), "+f"(c[1]), "+f"(c[2]), "+f"(c[3])
        : "r"(a[0]), "r"(a[1]), "r"(a[2]), "r"(a[3]), "r"(b[0]), "r"(b[1]));
}

#define PITCH 40                 // floats per smem row (160B, 16B-aligned, swizzle-friendly)
#define TILEF (128*PITCH)        // floats per 128x32 tile
#define GEMM_SMEM (4*TILEF*4)    // 2 buffers x (A+B) = 81920 B

// cp.async 16B stage of a 128x32 fp32 chunk into swizzled smem tile
__device__ __forceinline__ void stage_cp(uint32_t s, const float* __restrict__ g,
                                         size_t ld, int tid) {
    #pragma unroll
    for (int i = 0; i < 4; i++) {
        int idx = tid + i * 256;
        int r = idx >> 3;
        int c4 = (idx & 7) ^ ((r >> 2) & 1);     // flip k-bit2 on rows with bit2 set
        uint32_t dst = s + (uint32_t)(r * PITCH + c4 * 4) * 4u;
        const float* src = g + (size_t)r * ld + (idx & 7) * 4;
        asm volatile("cp.async.ca.shared.global [%0], [%1], 16;" :: "r"(dst), "l"(src));
    }
}
#define CP_COMMIT() asm volatile("cp.async.commit_group;" ::: "memory")

// warp-tile compute: 32(M) x 64(N), one BK=32 slab
__device__ __forceinline__ void compute_tile(const float* __restrict__ As,
                                             const float* __restrict__ Bs,
                                             int wm, int wn, int tr, int tc, int kflip,
                                             float c[2][8][4]) {
    #pragma unroll
    for (int kk = 0; kk < 4; kk++) {
        const int k0 = (kk * 8 + tc) ^ kflip;
        const int k1 = (kk * 8 + tc + 4) ^ kflip;
        uint32_t a[2][4], b[8][2];
        #pragma unroll
        for (int mt = 0; mt < 2; mt++) {
            const int r0 = wm * 32 + mt * 16 + tr;
            a[mt][0] = __float_as_uint(As[r0 * PITCH + k0]);
            a[mt][1] = __float_as_uint(As[(r0 + 8) * PITCH + k0]);
            a[mt][2] = __float_as_uint(As[r0 * PITCH + k1]);
            a[mt][3] = __float_as_uint(As[(r0 + 8) * PITCH + k1]);
        }
        #pragma unroll
        for (int nt = 0; nt < 8; nt++) {
            const int rn = wn * 64 + nt * 8 + tr;
            b[nt][0] = __float_as_uint(Bs[rn * PITCH + k0]);
            b[nt][1] = __float_as_uint(Bs[rn * PITCH + k1]);
        }
        #pragma unroll
        for (int mt = 0; mt < 2; mt++)
            #pragma unroll
            for (int nt = 0; nt < 8; nt++)
                mma8(c[mt][nt], a[mt], b[nt]);
    }
}

// full block GEMM mainloop: C[128x128] = A[128xK] * B[128xK]^T
__device__ __forceinline__ void gemm_main(const float* __restrict__ A, size_t lda,
                                          const float* __restrict__ B, size_t ldb,
                                          int nkb, float* sm, int tid,
                                          float c[2][8][4]) {
    const uint32_t smb = smem_u32(sm);
    float* bufA[2] = { sm,             sm + 2 * TILEF };
    float* bufB[2] = { sm + TILEF,     sm + 3 * TILEF };
    const uint32_t sbA[2] = { smb,                    smb + 2 * TILEF * 4 };
    const uint32_t sbB[2] = { smb + TILEF * 4,        smb + 3 * TILEF * 4 };
    const int wid = tid >> 5, lane = tid & 31;
    const int wm = wid & 3, wn = wid >> 2;
    const int tr = lane >> 2, tc = lane & 3;
    const int kflip = ((tr >> 2) & 1) << 2;

    stage_cp(sbA[0], A, lda, tid);
    stage_cp(sbB[0], B, ldb, tid);
    CP_COMMIT();

    for (int kb = 0; kb < nkb; kb++) {
        const int cur = kb & 1, nxt = cur ^ 1;
        const bool more = (kb + 1 < nkb);
        if (more) {
            stage_cp(sbA[nxt], A + (size_t)(kb + 1) * 32, lda, tid);
            stage_cp(sbB[nxt], B + (size_t)(kb + 1) * 32, ldb, tid);
            CP_COMMIT();
            asm volatile("cp.async.wait_group 1;" ::: "memory");
        } else {
            asm volatile("cp.async.wait_group 0;" ::: "memory");
        }
        __syncthreads();
        compute_tile(bufA[cur], bufB[cur], wm, wn, tr, tc, kflip, c);
        __syncthreads();
    }
}

// ---------------- small prep kernels ----------------
__global__ void roundx_kernel(const float* __restrict__ x) {
    size_t i = ((size_t)blockIdx.x * blockDim.x + threadIdx.x) * 4;
    float4 f = *(const float4*)(x + i);
    f.x = rna(f.x); f.y = rna(f.y); f.z = rna(f.z); f.w = rna(f.w);
    *(float4*)(g_x + i) = f;
}

__global__ void transW_kernel(const float* __restrict__ Wq, const float* __restrict__ Wk,
                              const float* __restrict__ Wv) {
    __shared__ float t[32][33];
    const int sel = blockIdx.z;
    const float* W = (sel == 0) ? Wq : (sel == 1) ? Wk : Wv;
    const int k0 = blockIdx.x * 32, n0 = blockIdx.y * 32;
    const int tx = threadIdx.x, ty = threadIdx.y;
    #pragma unroll
    for (int j = 0; j < 4; j++)
        t[ty + 8*j][tx] = W[(size_t)(k0 + ty + 8*j) * HH + n0 + tx];
    __syncthreads();
    #pragma unroll
    for (int j = 0; j < 4; j++)
        g_Wt[(size_t)sel * HH * DD + (size_t)(n0 + ty + 8*j) * DD + k0 + tx] =
            rna(t[tx][ty + 8*j]);
}

__global__ void scaleV_kernel() {
    __shared__ float t[32][33];
    const int b = blockIdx.z;
    const int k0 = blockIdx.x * 32, h0 = blockIdx.y * 32;
    const int tx = threadIdx.x, ty = threadIdx.y;
    #pragma unroll
    for (int j = 0; j < 4; j++) {
        int kk = k0 + ty + 8*j;
        float inv = 1.0f / g_colsum[(size_t)b * TT + kk];
        t[ty + 8*j][tx] = g_v[((size_t)b * TT + kk) * HH + h0 + tx] * inv;
    }
    __syncthreads();
    #pragma unroll
    for (int j = 0; j < 4; j++)
        g_Vt[((size_t)b * HH + h0 + ty + 8*j) * TT + k0 + tx] = rna(t[tx][ty + 8*j]);
}

// colsum[b,k] = sum_{q>=k} E[b,q,k]
__global__ __launch_bounds__(128) void colsum_kernel() {
    const int k0 = blockIdx.x * 128, b = blockIdx.y;
    const int k = k0 + threadIdx.x;
    const float* p = g_E + ((size_t)b * TT + k0) * TT + k;
    const int n = TT - k0;
    float s0 = 0.f, s1 = 0.f, s2 = 0.f, s3 = 0.f;
    for (int i = 0; i < n; i += 4) {
        s0 += p[0];
        s1 += p[(size_t)TT];
        s2 += p[2 * (size_t)TT];
        s3 += p[3 * (size_t)TT];
        p += 4 * (size_t)TT;
    }
    g_colsum[(size_t)b * TT + k] = (s0 + s1) + (s2 + s3);
}

// ---------------- GEMM kernels ----------------
__global__ __launch_bounds__(256, 2) void proj_tc(const float* __restrict__ bq,
                                                  const float* __restrict__ bk,
                                                  const float* __restrict__ bv) {
    extern __shared__ float sm[];
    const int tid = threadIdx.x;
    const int sel = blockIdx.y;
    const int row0 = blockIdx.x * 128;

    float c[2][8][4];
    #pragma unroll
    for (int m = 0; m < 2; m++)
        #pragma unroll
        for (int n = 0; n < 8; n++)
            #pragma unroll
            for (int i = 0; i < 4; i++) c[m][n][i] = 0.f;

    gemm_main(g_x + (size_t)row0 * DD, DD,
              g_Wt + (size_t)sel * HH * DD, DD, DD / 32, sm, tid, c);

    const int wid = tid >> 5, lane = tid & 31;
    const int wm = wid & 3, wn = wid >> 2;
    const int tr = lane >> 2, tc = lane & 3;
    const float* bias = (sel == 0) ? bq : (sel == 1) ? bk : bv;
    const float sc = (sel == 0) ? 0.08838834764831845f : 1.0f;
    float* dst = (sel == 0) ? g_q : (sel == 1) ? g_k : g_v;
    const bool doRound = (sel != 2);   // v gets rounded later (after /colsum)

    #pragma unroll
    for (int mt = 0; mt < 2; mt++) {
        const int row = row0 + wm * 32 + mt * 16 + tr;
        #pragma unroll
        for (int nt = 0; nt < 8; nt++) {
            const int col = wn * 64 + nt * 8 + tc * 2;
            const float b0 = bias[col], b1 = bias[col + 1];
            float2 lo, hi;
            lo.x = (c[mt][nt][0] + b0) * sc;
            lo.y = (c[mt][nt][1] + b1) * sc;
            hi.x = (c[mt][nt][2] + b0) * sc;
            hi.y = (c[mt][nt][3] + b1) * sc;
            if (doRound) {
                lo.x = rna(lo.x); lo.y = rna(lo.y);
                hi.x = rna(hi.x); hi.y = rna(hi.y);
            }
            *(float2*)(dst + (size_t)row * HH + col) = lo;
            *(float2*)(dst + (size_t)(row + 8) * HH + col) = hi;
        }
    }
}

__global__ __launch_bounds__(256, 2) void scores_tc() {
    const int kt = blockIdx.x, qt = blockIdx.y, b = blockIdx.z;
    if (qt < kt) return;
    extern __shared__ float sm[];
    const int tid = threadIdx.x;
    const int q0 = qt * 128, k0 = kt * 128;

    float c[2][8][4];
    #pragma unroll
    for (int m = 0; m < 2; m++)
        #pragma unroll
        for (int n = 0; n < 8; n++)
            #pragma unroll
            for (int i = 0; i < 4; i++) c[m][n][i] = 0.f;

    gemm_main(g_q + ((size_t)b * TT + q0) * HH, HH,
              g_k + ((size_t)b * TT + k0) * HH, HH, HH / 32, sm, tid, c);

    const int wid = tid >> 5, lane = tid & 31;
    const int wm = wid & 3, wn = wid >> 2;
    const int tr = lane >> 2, tc = lane & 3;

    #pragma unroll
    for (int mt = 0; mt < 2; mt++) {
        const int q = q0 + wm * 32 + mt * 16 + tr;
        #pragma unroll
        for (int nt = 0; nt < 8; nt++) {
            const int k = k0 + wn * 64 + nt * 8 + tc * 2;
            float2 lo, hi;
            lo.x = (q     >= k    ) ? rna(__expf(c[mt][nt][0])) : 0.f;
            lo.y = (q     >= k + 1) ? rna(__expf(c[mt][nt][1])) : 0.f;
            hi.x = (q + 8 >= k    ) ? rna(__expf(c[mt][nt][2])) : 0.f;
            hi.y = (q + 8 >= k + 1) ? rna(__expf(c[mt][nt][3])) : 0.f;
            *(float2*)(g_E + ((size_t)b * TT + q) * TT + k) = lo;
            *(float2*)(g_E + ((size_t)b * TT + q + 8) * TT + k) = hi;
        }
    }
}

__global__ __launch_bounds__(256, 2) void pv_tc(float* __restrict__ out) {
    extern __shared__ float sm[];
    const int tid = threadIdx.x;
    const int qt = blockIdx.x, b = blockIdx.y;
    const int q0 = qt * 128;

    float c[2][8][4];
    #pragma unroll
    for (int m = 0; m < 2; m++)
        #pragma unroll
        for (int n = 0; n < 8; n++)
            #pragma unroll
            for (int i = 0; i < 4; i++) c[m][n][i] = 0.f;

    gemm_main(g_E + ((size_t)b * TT + q0) * TT, TT,
              g_Vt + (size_t)b * HH * TT, TT, (qt + 1) * 4, sm, tid, c);

    const int wid = tid >> 5, lane = tid & 31;
    const int wm = wid & 3, wn = wid >> 2;
    const int tr = lane >> 2, tc = lane & 3;

    #pragma unroll
    for (int mt = 0; mt < 2; mt++) {
        const int q = q0 + wm * 32 + mt * 16 + tr;
        #pragma unroll
        for (int nt = 0; nt < 8; nt++) {
            const int col = wn * 64 + nt * 8 + tc * 2;
            float2 lo = { c[mt][nt][0], c[mt][nt][1] };
            float2 hi = { c[mt][nt][2], c[mt][nt][3] };
            *(float2*)(out + ((size_t)b * TT + q) * HH + col) = lo;
            *(float2*)(out + ((size_t)b * TT + q + 8) * HH + col) = hi;
        }
    }
}

// ---------------- launch ----------------
extern "C" void kernel_launch(void* const* d_in, const int* in_sizes, int n_in,
                              void* d_out, int out_size) {
    const float* x  = (const float*)d_in[0];
    const float* Wk = (const float*)d_in[1];
    const float* bk = (const float*)d_in[2];
    const float* Wq = (const float*)d_in[3];
    const float* bq = (const float*)d_in[4];
    const float* Wv = (const float*)d_in[5];
    const float* bv = (const float*)d_in[6];
    float* out = (float*)d_out;

    cudaFuncSetAttribute(proj_tc,   cudaFuncAttributeMaxDynamicSharedMemorySize, GEMM_SMEM);
    cudaFuncSetAttribute(scores_tc, cudaFuncAttributeMaxDynamicSharedMemorySize, GEMM_SMEM);
    cudaFuncSetAttribute(pv_tc,     cudaFuncAttributeMaxDynamicSharedMemorySize, GEMM_SMEM);

    roundx_kernel<<<(size_t)BT * DD / 1024, 256>>>(x);
    transW_kernel<<<dim3(DD/32, HH/32, 3), dim3(32, 8)>>>(Wq, Wk, Wv);
    proj_tc<<<dim3(BT/128, 3), 256, GEMM_SMEM>>>(bq, bk, bv);
    scores_tc<<<dim3(TT/128, TT/128, BB), 256, GEMM_SMEM>>>();
    colsum_kernel<<<dim3(TT/128, BB), 128>>>();
    scaleV_kernel<<<dim3(TT/32, HH/32, BB), dim3(32, 8)>>>();
    pv_tc<<<dim3(TT/128, BB), 256, GEMM_SMEM>>>(out);
}

// round 4
// speedup vs baseline: 5.6896x; 1.1906x over previous
#include <cuda_runtime.h>
#include <cstdint>

#define BB 16
#define TT 2048
#define DD 1024
#define HH 128
#define BT (BB*TT)

// ---------------- device scratch (allocation-free rule) ----------------
__device__ __align__(128) float g_x[(size_t)BT*DD];       // tf32-rounded copy of x
__device__ __align__(128) float g_q[(size_t)BT*HH];       // tf32-rounded, pre-scaled
__device__ __align__(128) float g_k[(size_t)BT*HH];       // tf32-rounded
__device__ __align__(128) float g_v[(size_t)BT*HH];       // fp32 (rounded later in Vt)
__device__ __align__(128) float g_Wt[3*(size_t)HH*DD];    // [sel][n][k], tf32-rounded
__device__ __align__(128) float g_Vt[(size_t)BB*HH*TT];   // [b][h][k] = v/colsum, tf32-rounded
__device__ __align__(128) float g_colsum[BT];
__device__ __align__(128) float g_E[(size_t)BB*TT*TT];    // exp(masked S), tf32-rounded

// ---------------- helpers ----------------
__device__ __forceinline__ float rna(float x) {
    uint32_t u;
    asm("cvt.rna.tf32.f32 %0, %1;" : "=r"(u) : "f"(x));
    return __uint_as_float(u);
}
__device__ __forceinline__ uint32_t smem_u32(const void* p) {
    uint32_t a;
    asm("{ .reg .u64 t; cvta.to.shared.u64 t, %1; cvt.u32.u64 %0, t; }" : "=r"(a) : "l"(p));
    return a;
}
__device__ __forceinline__ void mma8(float* c, const uint32_t* a, const uint32_t* b) {
    asm volatile(
        "mma.sync.aligned.m16n8k8.row.col.f32.tf32.tf32.f32 "
        "{%0,%1,%2,%3}, {%4,%5,%6,%7}, {%8,%9}, {%0,%1,%2,%3};"
        : "+f"(c[0]), "+f"(c[1]), "+f"(c[2]), "+f"(c[3])
        : "r"(a[0]), "r"(a[1]), "r"(a[2]), "r"(a[3]), "r"(b[0]), "r"(b[1]));
}

#define PITCH 36                 // floats per smem row: bank = 4r+c -> conflict-free
#define TILEF (128*PITCH)        // floats per 128x32 tile (18432 B)
#define NSTAGE 3
#define GEMM_SMEM (NSTAGE*2*TILEF*4)   // 110592 B

// cp.async 16B stage of a 128x32 fp32 chunk into PITCH-36 smem tile (128 thr)
__device__ __forceinline__ void stage_cp(uint32_t s, const float* __restrict__ g,
                                         size_t ld, int tid) {
    #pragma unroll
    for (int i = 0; i < 8; i++) {
        int idx = tid + i * 128;
        int r = idx >> 3;
        int c4 = idx & 7;
        uint32_t dst = s + (uint32_t)(r * PITCH + c4 * 4) * 4u;
        const float* src = g + (size_t)r * ld + c4 * 4;
        asm volatile("cp.async.cg.shared.global [%0], [%1], 16;" :: "r"(dst), "l"(src));
    }
}
#define CP_COMMIT() asm volatile("cp.async.commit_group;" ::: "memory")

// warp-tile compute: 64(M) x 64(N), one BK=32 slab. 4 warps: wm=wid&1, wn=wid>>1
__device__ __forceinline__ void compute_tile(const float* __restrict__ As,
                                             const float* __restrict__ Bs,
                                             int wm, int wn, int tr, int tc,
                                             float c[4][8][4]) {
    const float* Aw = As + (wm * 64 + tr) * PITCH;
    const float* Bw = Bs + (wn * 64 + tr) * PITCH;
    #pragma unroll
    for (int kk = 0; kk < 4; kk++) {
        const int k0 = kk * 8 + tc;
        const int k1 = k0 + 4;
        uint32_t a[4][4], b[8][2];
        #pragma unroll
        for (int mt = 0; mt < 4; mt++) {
            const float* Ar = Aw + mt * 16 * PITCH;
            a[mt][0] = __float_as_uint(Ar[k0]);
            a[mt][1] = __float_as_uint(Ar[8 * PITCH + k0]);
            a[mt][2] = __float_as_uint(Ar[k1]);
            a[mt][3] = __float_as_uint(Ar[8 * PITCH + k1]);
        }
        #pragma unroll
        for (int nt = 0; nt < 8; nt++) {
            const float* Br = Bw + nt * 8 * PITCH;
            b[nt][0] = __float_as_uint(Br[k0]);
            b[nt][1] = __float_as_uint(Br[k1]);
        }
        #pragma unroll
        for (int mt = 0; mt < 4; mt++)
            #pragma unroll
            for (int nt = 0; nt < 8; nt++)
                mma8(c[mt][nt], a[mt], b[nt]);
    }
}

// block GEMM mainloop: C[128x128] = A[128xK] * B[128xK]^T, 128 threads, 3 stages
__device__ __forceinline__ void gemm_main(const float* __restrict__ A, size_t lda,
                                          const float* __restrict__ B, size_t ldb,
                                          int nkb, float* sm, int tid,
                                          float c[4][8][4]) {
    const uint32_t smb = smem_u32(sm);
    const int wid = tid >> 5, lane = tid & 31;
    const int wm = wid & 1, wn = wid >> 1;
    const int tr = lane >> 2, tc = lane & 3;

    // prologue: stages 0,1
    stage_cp(smb,                 A, lda, tid);
    stage_cp(smb + TILEF * 4,     B, ldb, tid);
    CP_COMMIT();
    if (nkb > 1) {
        stage_cp(smb + 2 * TILEF * 4, A + 32, lda, tid);
        stage_cp(smb + 3 * TILEF * 4, B + 32, ldb, tid);
    }
    CP_COMMIT();

    for (int kb = 0; kb < nkb; kb++) {
        asm volatile("cp.async.wait_group 1;" ::: "memory");
        __syncthreads();
        if (kb + 2 < nkb) {
            const int st = (kb + 2) % NSTAGE;
            stage_cp(smb + (2 * st) * TILEF * 4,     A + (size_t)(kb + 2) * 32, lda, tid);
            stage_cp(smb + (2 * st + 1) * TILEF * 4, B + (size_t)(kb + 2) * 32, ldb, tid);
        }
        CP_COMMIT();
        const int cs = kb % NSTAGE;
        compute_tile(sm + (2 * cs) * TILEF, sm + (2 * cs + 1) * TILEF, wm, wn, tr, tc, c);
    }
}

#define ZERO_ACC(c) do { \
    _Pragma("unroll") for (int m = 0; m < 4; m++) \
    _Pragma("unroll") for (int n = 0; n < 8; n++) \
    _Pragma("unroll") for (int i = 0; i < 4; i++) (c)[m][n][i] = 0.f; } while (0)

// ---------------- small prep kernels ----------------
__global__ void roundx_kernel(const float* __restrict__ x) {
    size_t i = ((size_t)blockIdx.x * blockDim.x + threadIdx.x) * 4;
    float4 f = *(const float4*)(x + i);
    f.x = rna(f.x); f.y = rna(f.y); f.z = rna(f.z); f.w = rna(f.w);
    *(float4*)(g_x + i) = f;
}

__global__ void transW_kernel(const float* __restrict__ Wq, const float* __restrict__ Wk,
                              const float* __restrict__ Wv) {
    __shared__ float t[32][33];
    const int sel = blockIdx.z;
    const float* W = (sel == 0) ? Wq : (sel == 1) ? Wk : Wv;
    const int k0 = blockIdx.x * 32, n0 = blockIdx.y * 32;
    const int tx = threadIdx.x, ty = threadIdx.y;
    #pragma unroll
    for (int j = 0; j < 4; j++)
        t[ty + 8*j][tx] = W[(size_t)(k0 + ty + 8*j) * HH + n0 + tx];
    __syncthreads();
    #pragma unroll
    for (int j = 0; j < 4; j++)
        g_Wt[(size_t)sel * HH * DD + (size_t)(n0 + ty + 8*j) * DD + k0 + tx] =
            rna(t[tx][ty + 8*j]);
}

__global__ void scaleV_kernel() {
    __shared__ float t[32][33];
    const int b = blockIdx.z;
    const int k0 = blockIdx.x * 32, h0 = blockIdx.y * 32;
    const int tx = threadIdx.x, ty = threadIdx.y;
    #pragma unroll
    for (int j = 0; j < 4; j++) {
        int kk = k0 + ty + 8*j;
        float inv = 1.0f / g_colsum[(size_t)b * TT + kk];
        t[ty + 8*j][tx] = g_v[((size_t)b * TT + kk) * HH + h0 + tx] * inv;
    }
    __syncthreads();
    #pragma unroll
    for (int j = 0; j < 4; j++)
        g_Vt[((size_t)b * HH + h0 + ty + 8*j) * TT + k0 + tx] = rna(t[tx][ty + 8*j]);
}

// colsum[b,k] = sum_{q>=k} E[b,q,k]
__global__ __launch_bounds__(128) void colsum_kernel() {
    const int k0 = blockIdx.x * 128, b = blockIdx.y;
    const int k = k0 + threadIdx.x;
    const float* p = g_E + ((size_t)b * TT + k0) * TT + k;
    const int n = TT - k0;
    float s0 = 0.f, s1 = 0.f, s2 = 0.f, s3 = 0.f;
    for (int i = 0; i < n; i += 4) {
        s0 += p[0];
        s1 += p[(size_t)TT];
        s2 += p[2 * (size_t)TT];
        s3 += p[3 * (size_t)TT];
        p += 4 * (size_t)TT;
    }
    g_colsum[(size_t)b * TT + k] = (s0 + s1) + (s2 + s3);
}

// ---------------- GEMM kernels (128 threads, warp tile 64x64) ----------------
__global__ __launch_bounds__(128, 2) void proj_tc(const float* __restrict__ bq,
                                                  const float* __restrict__ bk,
                                                  const float* __restrict__ bv) {
    extern __shared__ float sm[];
    const int tid = threadIdx.x;
    const int sel = blockIdx.y;
    const int row0 = blockIdx.x * 128;

    float c[4][8][4];
    ZERO_ACC(c);
    gemm_main(g_x + (size_t)row0 * DD, DD,
              g_Wt + (size_t)sel * HH * DD, DD, DD / 32, sm, tid, c);

    const int wid = tid >> 5, lane = tid & 31;
    const int wm = wid & 1, wn = wid >> 1;
    const int tr = lane >> 2, tc = lane & 3;
    const float* bias = (sel == 0) ? bq : (sel == 1) ? bk : bv;
    const float sc = (sel == 0) ? 0.08838834764831845f : 1.0f;
    float* dst = (sel == 0) ? g_q : (sel == 1) ? g_k : g_v;
    const bool doRound = (sel != 2);

    #pragma unroll
    for (int mt = 0; mt < 4; mt++) {
        const int row = row0 + wm * 64 + mt * 16 + tr;
        #pragma unroll
        for (int nt = 0; nt < 8; nt++) {
            const int col = wn * 64 + nt * 8 + tc * 2;
            const float b0 = bias[col], b1 = bias[col + 1];
            float2 lo, hi;
            lo.x = (c[mt][nt][0] + b0) * sc;
            lo.y = (c[mt][nt][1] + b1) * sc;
            hi.x = (c[mt][nt][2] + b0) * sc;
            hi.y = (c[mt][nt][3] + b1) * sc;
            if (doRound) {
                lo.x = rna(lo.x); lo.y = rna(lo.y);
                hi.x = rna(hi.x); hi.y = rna(hi.y);
            }
            *(float2*)(dst + (size_t)row * HH + col) = lo;
            *(float2*)(dst + (size_t)(row + 8) * HH + col) = hi;
        }
    }
}

__global__ __launch_bounds__(128, 2) void scores_tc() {
    const int kt = blockIdx.x, qt = blockIdx.y, b = blockIdx.z;
    if (qt < kt) return;
    extern __shared__ float sm[];
    const int tid = threadIdx.x;
    const int q0 = qt * 128, k0 = kt * 128;

    float c[4][8][4];
    ZERO_ACC(c);
    gemm_main(g_q + ((size_t)b * TT + q0) * HH, HH,
              g_k + ((size_t)b * TT + k0) * HH, HH, HH / 32, sm, tid, c);

    const int wid = tid >> 5, lane = tid & 31;
    const int wm = wid & 1, wn = wid >> 1;
    const int tr = lane >> 2, tc = lane & 3;

    #pragma unroll
    for (int mt = 0; mt < 4; mt++) {
        const int q = q0 + wm * 64 + mt * 16 + tr;
        #pragma unroll
        for (int nt = 0; nt < 8; nt++) {
            const int k = k0 + wn * 64 + nt * 8 + tc * 2;
            float2 lo, hi;
            lo.x = (q     >= k    ) ? rna(__expf(c[mt][nt][0])) : 0.f;
            lo.y = (q     >= k + 1) ? rna(__expf(c[mt][nt][1])) : 0.f;
            hi.x = (q + 8 >= k    ) ? rna(__expf(c[mt][nt][2])) : 0.f;
            hi.y = (q + 8 >= k + 1) ? rna(__expf(c[mt][nt][3])) : 0.f;
            *(float2*)(g_E + ((size_t)b * TT + q) * TT + k) = lo;
            *(float2*)(g_E + ((size_t)b * TT + q + 8) * TT + k) = hi;
        }
    }
}

__global__ __launch_bounds__(128, 2) void pv_tc(float* __restrict__ out) {
    extern __shared__ float sm[];
    const int tid = threadIdx.x;
    const int qt = blockIdx.x, b = blockIdx.y;
    const int q0 = qt * 128;

    float c[4][8][4];
    ZERO_ACC(c);
    gemm_main(g_E + ((size_t)b * TT + q0) * TT, TT,
              g_Vt + (size_t)b * HH * TT, TT, (qt + 1) * 4, sm, tid, c);

    const int wid = tid >> 5, lane = tid & 31;
    const int wm = wid & 1, wn = wid >> 1;
    const int tr = lane >> 2, tc = lane & 3;

    #pragma unroll
    for (int mt = 0; mt < 4; mt++) {
        const int q = q0 + wm * 64 + mt * 16 + tr;
        #pragma unroll
        for (int nt = 0; nt < 8; nt++) {
            const int col = wn * 64 + nt * 8 + tc * 2;
            float2 lo = { c[mt][nt][0], c[mt][nt][1] };
            float2 hi = { c[mt][nt][2], c[mt][nt][3] };
            *(float2*)(out + ((size_t)b * TT + q) * HH + col) = lo;
            *(float2*)(out + ((size_t)b * TT + q + 8) * HH + col) = hi;
        }
    }
}

// ---------------- launch ----------------
extern "C" void kernel_launch(void* const* d_in, const int* in_sizes, int n_in,
                              void* d_out, int out_size) {
    const float* x  = (const float*)d_in[0];
    const float* Wk = (const float*)d_in[1];
    const float* bk = (const float*)d_in[2];
    const float* Wq = (const float*)d_in[3];
    const float* bq = (const float*)d_in[4];
    const float* Wv = (const float*)d_in[5];
    const float* bv = (const float*)d_in[6];
    float* out = (float*)d_out;

    cudaFuncSetAttribute(proj_tc,   cudaFuncAttributeMaxDynamicSharedMemorySize, GEMM_SMEM);
    cudaFuncSetAttribute(scores_tc, cudaFuncAttributeMaxDynamicSharedMemorySize, GEMM_SMEM);
    cudaFuncSetAttribute(pv_tc,     cudaFuncAttributeMaxDynamicSharedMemorySize, GEMM_SMEM);

    roundx_kernel<<<(size_t)BT * DD / 1024, 256>>>(x);
    transW_kernel<<<dim3(DD/32, HH/32, 3), dim3(32, 8)>>>(Wq, Wk, Wv);
    proj_tc<<<dim3(BT/128, 3), 128, GEMM_SMEM>>>(bq, bk, bv);
    scores_tc<<<dim3(TT/128, TT/128, BB), 128, GEMM_SMEM>>>();
    colsum_kernel<<<dim3(TT/128, BB), 128>>>();
    scaleV_kernel<<<dim3(TT/32, HH/32, BB), dim3(32, 8)>>>();
    pv_tc<<<dim3(TT/128, BB), 128, GEMM_SMEM>>>(out);
}

// round 5
// speedup vs baseline: 9.3078x; 1.6359x over previous
#include <cuda_runtime.h>
#include <cuda_fp16.h>
#include <cstdint>

#define BB 16
#define TT 2048
#define DD 1024
#define HH 128
#define BT (BB*TT)

// ---------------- device scratch (allocation-free rule) ----------------
__device__ __align__(128) __half g_xh[(size_t)BT*DD];      // half copy of x
__device__ __align__(128) __half g_qh[(size_t)BT*HH];      // half, pre-scaled
__device__ __align__(128) __half g_kh[(size_t)BT*HH];
__device__ __align__(128) float  g_v [(size_t)BT*HH];      // fp32 (scaled later)
__device__ __align__(128) __half g_Wth[3*(size_t)HH*DD];   // [sel][n][k]
__device__ __align__(128) __half g_Vth[(size_t)BB*HH*TT];  // [b][h][k] = v/colsum
__device__ __align__(128) float  g_colsum[BT];
__device__ __align__(128) __half g_Eh[(size_t)BB*TT*TT];   // exp(masked S)

// ---------------- helpers ----------------
__device__ __forceinline__ uint32_t smem_u32(const void* p) {
    uint32_t a;
    asm("{ .reg .u64 t; cvta.to.shared.u64 t, %1; cvt.u32.u64 %0, t; }" : "=r"(a) : "l"(p));
    return a;
}
__device__ __forceinline__ void ldsm4(uint32_t& r0, uint32_t& r1, uint32_t& r2, uint32_t& r3,
                                      uint32_t addr) {
    asm volatile("ldmatrix.sync.aligned.m8n8.x4.shared.b16 {%0,%1,%2,%3}, [%4];"
                 : "=r"(r0), "=r"(r1), "=r"(r2), "=r"(r3) : "r"(addr));
}
__device__ __forceinline__ void mma16(float* c, const uint32_t* a, const uint32_t* b) {
    asm volatile(
        "mma.sync.aligned.m16n8k16.row.col.f32.f16.f16.f32 "
        "{%0,%1,%2,%3}, {%4,%5,%6,%7}, {%8,%9}, {%0,%1,%2,%3};"
        : "+f"(c[0]), "+f"(c[1]), "+f"(c[2]), "+f"(c[3])
        : "r"(a[0]), "r"(a[1]), "r"(a[2]), "r"(a[3]), "r"(b[0]), "r"(b[1]));
}

#define PH 40                    // halves per smem row (80B): ldmatrix conflict-free
#define TILEH (128*PH)           // halves per 128x32 tile
#define TILEB (TILEH*2)          // 10240 B
#define NSTAGE 3
#define GEMM_SMEM (NSTAGE*2*TILEB)   // 61440 B

// cp.async 16B stage of a 128x32-half chunk (row stride ld halves), 128 threads
__device__ __forceinline__ void stage_cp(uint32_t s, const __half* __restrict__ g,
                                         size_t ld, int tid) {
    #pragma unroll
    for (int i = 0; i < 4; i++) {
        int idx = tid + i * 128;
        int r = idx >> 2, c8 = idx & 3;
        uint32_t dst = s + (uint32_t)(r * PH + c8 * 8) * 2u;
        const __half* src = g + (size_t)r * ld + c8 * 8;
        asm volatile("cp.async.cg.shared.global [%0], [%1], 16;" :: "r"(dst), "l"(src));
    }
}
#define CP_COMMIT() asm volatile("cp.async.commit_group;" ::: "memory")

// warp tile 64(M) x 64(N), one BK=32 slab (two k16 steps).
// aoff/boff: per-lane byte offsets within the A/B tile (precomputed).
__device__ __forceinline__ void compute_tile(uint32_t sA, uint32_t sB,
                                             uint32_t aoff, uint32_t boff,
                                             float c[4][8][4]) {
    #pragma unroll
    for (int ks = 0; ks < 2; ks++) {
        uint32_t a[4][4], b[8][2];
        #pragma unroll
        for (int mt = 0; mt < 4; mt++)
            ldsm4(a[mt][0], a[mt][1], a[mt][2], a[mt][3],
                  sA + aoff + mt * (16 * PH * 2) + ks * 32);
        #pragma unroll
        for (int np = 0; np < 4; np++)
            ldsm4(b[2*np][0], b[2*np][1], b[2*np+1][0], b[2*np+1][1],
                  sB + boff + np * (16 * PH * 2) + ks * 32);
        #pragma unroll
        for (int mt = 0; mt < 4; mt++)
            #pragma unroll
            for (int nt = 0; nt < 8; nt++)
                mma16(c[mt][nt], a[mt], b[nt]);
    }
}

// block GEMM: C[128x128] = A[128xK] * B[128xK]^T, 128 threads, 3 cp.async stages
__device__ __forceinline__ void gemm_main(const __half* __restrict__ A, size_t lda,
                                          const __half* __restrict__ B, size_t ldb,
                                          int nkb, int tid, float c[4][8][4]) {
    extern __shared__ __half smh[];
    const uint32_t smb = smem_u32(smh);
    const int wid = tid >> 5, lane = tid & 31;
    const int wm = wid & 1, wn = wid >> 1;
    // ldmatrix lane offsets (bytes within tile)
    const uint32_t aoff = ((wm * 64 + (lane & 15)) * PH + (lane >> 4) * 8) * 2u;
    const uint32_t boff = ((wn * 64 + (lane & 7) + ((lane >> 4) << 3)) * PH
                           + ((lane >> 3) & 1) * 8) * 2u;

    stage_cp(smb,         A, lda, tid);
    stage_cp(smb + TILEB, B, ldb, tid);
    CP_COMMIT();
    if (nkb > 1) {
        stage_cp(smb + 2 * TILEB, A + 32, lda, tid);
        stage_cp(smb + 3 * TILEB, B + 32, ldb, tid);
    }
    CP_COMMIT();

    for (int kb = 0; kb < nkb; kb++) {
        asm volatile("cp.async.wait_group 1;" ::: "memory");
        __syncthreads();
        if (kb + 2 < nkb) {
            const int st = (kb + 2) % NSTAGE;
            stage_cp(smb + (2 * st) * TILEB,     A + (size_t)(kb + 2) * 32, lda, tid);
            stage_cp(smb + (2 * st + 1) * TILEB, B + (size_t)(kb + 2) * 32, ldb, tid);
        }
        CP_COMMIT();
        const int cs = kb % NSTAGE;
        compute_tile(smb + (2 * cs) * TILEB, smb + (2 * cs + 1) * TILEB, aoff, boff, c);
    }
}

#define ZERO_ACC(c) do { \
    _Pragma("unroll") for (int m = 0; m < 4; m++) \
    _Pragma("unroll") for (int n = 0; n < 8; n++) \
    _Pragma("unroll") for (int i = 0; i < 4; i++) (c)[m][n][i] = 0.f; } while (0)

// ---------------- prep kernels ----------------
__global__ void roundx_kernel(const float* __restrict__ x) {
    size_t i = ((size_t)blockIdx.x * blockDim.x + threadIdx.x) * 4;
    float4 f = *(const float4*)(x + i);
    __half2 h0 = __floats2half2_rn(f.x, f.y);
    __half2 h1 = __floats2half2_rn(f.z, f.w);
    *(__half2*)(g_xh + i)     = h0;
    *(__half2*)(g_xh + i + 2) = h1;
}

__global__ void transW_kernel(const float* __restrict__ Wq, const float* __restrict__ Wk,
                              const float* __restrict__ Wv) {
    __shared__ float t[32][33];
    const int sel = blockIdx.z;
    const float* W = (sel == 0) ? Wq : (sel == 1) ? Wk : Wv;
    const int k0 = blockIdx.x * 32, n0 = blockIdx.y * 32;
    const int tx = threadIdx.x, ty = threadIdx.y;
    #pragma unroll
    for (int j = 0; j < 4; j++)
        t[ty + 8*j][tx] = W[(size_t)(k0 + ty + 8*j) * HH + n0 + tx];
    __syncthreads();
    #pragma unroll
    for (int j = 0; j < 4; j++)
        g_Wth[(size_t)sel * HH * DD + (size_t)(n0 + ty + 8*j) * DD + k0 + tx] =
            __float2half_rn(t[tx][ty + 8*j]);
}

__global__ void scaleV_kernel() {
    __shared__ float t[32][33];
    const int b = blockIdx.z;
    const int k0 = blockIdx.x * 32, h0 = blockIdx.y * 32;
    const int tx = threadIdx.x, ty = threadIdx.y;
    #pragma unroll
    for (int j = 0; j < 4; j++) {
        int kk = k0 + ty + 8*j;
        float inv = 1.0f / g_colsum[(size_t)b * TT + kk];
        t[ty + 8*j][tx] = g_v[((size_t)b * TT + kk) * HH + h0 + tx] * inv;
    }
    __syncthreads();
    #pragma unroll
    for (int j = 0; j < 4; j++)
        g_Vth[((size_t)b * HH + h0 + ty + 8*j) * TT + k0 + tx] =
            __float2half_rn(t[tx][ty + 8*j]);
}

// colsum[b,k] = sum_{q>=k} E[b,q,k]
__global__ __launch_bounds__(128) void colsum_kernel() {
    const int k0 = blockIdx.x * 128, b = blockIdx.y;
    const int k = k0 + threadIdx.x;
    const __half* p = g_Eh + ((size_t)b * TT + k0) * TT + k;
    const int n = TT - k0;
    float s0 = 0.f, s1 = 0.f, s2 = 0.f, s3 = 0.f;
    for (int i = 0; i < n; i += 4) {
        s0 += __half2float(p[0]);
        s1 += __half2float(p[(size_t)TT]);
        s2 += __half2float(p[2 * (size_t)TT]);
        s3 += __half2float(p[3 * (size_t)TT]);
        p += 4 * (size_t)TT;
    }
    g_colsum[(size_t)b * TT + k] = (s0 + s1) + (s2 + s3);
}

// ---------------- GEMM kernels (128 threads, warp tile 64x64, fp16 mma) ----------------
__global__ __launch_bounds__(128, 2) void proj_tc(const float* __restrict__ bq,
                                                  const float* __restrict__ bk,
                                                  const float* __restrict__ bv) {
    const int tid = threadIdx.x;
    const int sel = blockIdx.y;
    const int row0 = blockIdx.x * 128;

    float c[4][8][4];
    ZERO_ACC(c);
    gemm_main(g_xh + (size_t)row0 * DD, DD,
              g_Wth + (size_t)sel * HH * DD, DD, DD / 32, tid, c);

    const int wid = tid >> 5, lane = tid & 31;
    const int wm = wid & 1, wn = wid >> 1;
    const int tr = lane >> 2, tc = lane & 3;
    const float* bias = (sel == 0) ? bq : (sel == 1) ? bk : bv;
    const float sc = (sel == 0) ? 0.08838834764831845f : 1.0f;

    #pragma unroll
    for (int mt = 0; mt < 4; mt++) {
        const int row = row0 + wm * 64 + mt * 16 + tr;
        #pragma unroll
        for (int nt = 0; nt < 8; nt++) {
            const int col = wn * 64 + nt * 8 + tc * 2;
            const float b0 = bias[col], b1 = bias[col + 1];
            float lx = (c[mt][nt][0] + b0) * sc;
            float ly = (c[mt][nt][1] + b1) * sc;
            float hx = (c[mt][nt][2] + b0) * sc;
            float hy = (c[mt][nt][3] + b1) * sc;
            if (sel != 2) {
                __half* dst = (sel == 0) ? g_qh : g_kh;
                *(__half2*)(dst + (size_t)row * HH + col)       = __floats2half2_rn(lx, ly);
                *(__half2*)(dst + (size_t)(row + 8) * HH + col) = __floats2half2_rn(hx, hy);
            } else {
                *(float2*)(g_v + (size_t)row * HH + col)       = make_float2(lx, ly);
                *(float2*)(g_v + (size_t)(row + 8) * HH + col) = make_float2(hx, hy);
            }
        }
    }
}

__global__ __launch_bounds__(128, 2) void scores_tc() {
    const int kt = blockIdx.x, qt = blockIdx.y, b = blockIdx.z;
    if (qt < kt) return;
    const int tid = threadIdx.x;
    const int q0 = qt * 128, k0 = kt * 128;

    float c[4][8][4];
    ZERO_ACC(c);
    gemm_main(g_qh + ((size_t)b * TT + q0) * HH, HH,
              g_kh + ((size_t)b * TT + k0) * HH, HH, HH / 32, tid, c);

    const int wid = tid >> 5, lane = tid & 31;
    const int wm = wid & 1, wn = wid >> 1;
    const int tr = lane >> 2, tc = lane & 3;

    #pragma unroll
    for (int mt = 0; mt < 4; mt++) {
        const int q = q0 + wm * 64 + mt * 16 + tr;
        #pragma unroll
        for (int nt = 0; nt < 8; nt++) {
            const int k = k0 + wn * 64 + nt * 8 + tc * 2;
            float lx = (q     >= k    ) ? __expf(c[mt][nt][0]) : 0.f;
            float ly = (q     >= k + 1) ? __expf(c[mt][nt][1]) : 0.f;
            float hx = (q + 8 >= k    ) ? __expf(c[mt][nt][2]) : 0.f;
            float hy = (q + 8 >= k + 1) ? __expf(c[mt][nt][3]) : 0.f;
            *(__half2*)(g_Eh + ((size_t)b * TT + q) * TT + k)       = __floats2half2_rn(lx, ly);
            *(__half2*)(g_Eh + ((size_t)b * TT + q + 8) * TT + k)   = __floats2half2_rn(hx, hy);
        }
    }
}

__global__ __launch_bounds__(128, 2) void pv_tc(float* __restrict__ out) {
    const int tid = threadIdx.x;
    const int qt = blockIdx.x, b = blockIdx.y;
    const int q0 = qt * 128;

    float c[4][8][4];
    ZERO_ACC(c);
    gemm_main(g_Eh + ((size_t)b * TT + q0) * TT, TT,
              g_Vth + (size_t)b * HH * TT, TT, (qt + 1) * 4, tid, c);

    const int wid = tid >> 5, lane = tid & 31;
    const int wm = wid & 1, wn = wid >> 1;
    const int tr = lane >> 2, tc = lane & 3;

    #pragma unroll
    for (int mt = 0; mt < 4; mt++) {
        const int q = q0 + wm * 64 + mt * 16 + tr;
        #pragma unroll
        for (int nt = 0; nt < 8; nt++) {
            const int col = wn * 64 + nt * 8 + tc * 2;
            *(float2*)(out + ((size_t)b * TT + q) * HH + col) =
                make_float2(c[mt][nt][0], c[mt][nt][1]);
            *(float2*)(out + ((size_t)b * TT + q + 8) * HH + col) =
                make_float2(c[mt][nt][2], c[mt][nt][3]);
        }
    }
}

// ---------------- launch ----------------
extern "C" void kernel_launch(void* const* d_in, const int* in_sizes, int n_in,
                              void* d_out, int out_size) {
    const float* x  = (const float*)d_in[0];
    const float* Wk = (const float*)d_in[1];
    const float* bk = (const float*)d_in[2];
    const float* Wq = (const float*)d_in[3];
    const float* bq = (const float*)d_in[4];
    const float* Wv = (const float*)d_in[5];
    const float* bv = (const float*)d_in[6];
    float* out = (float*)d_out;

    cudaFuncSetAttribute(proj_tc,   cudaFuncAttributeMaxDynamicSharedMemorySize, GEMM_SMEM);
    cudaFuncSetAttribute(scores_tc, cudaFuncAttributeMaxDynamicSharedMemorySize, GEMM_SMEM);
    cudaFuncSetAttribute(pv_tc,     cudaFuncAttributeMaxDynamicSharedMemorySize, GEMM_SMEM);

    roundx_kernel<<<(size_t)BT * DD / 1024, 256>>>(x);
    transW_kernel<<<dim3(DD/32, HH/32, 3), dim3(32, 8)>>>(Wq, Wk, Wv);
    proj_tc<<<dim3(BT/128, 3), 128, GEMM_SMEM>>>(bq, bk, bv);
    scores_tc<<<dim3(TT/128, TT/128, BB), 128, GEMM_SMEM>>>();
    colsum_kernel<<<dim3(TT/128, BB), 128>>>();
    scaleV_kernel<<<dim3(TT/32, HH/32, BB), dim3(32, 8)>>>();
    pv_tc<<<dim3(TT/128, BB), 128, GEMM_SMEM>>>(out);
}

// round 6
// speedup vs baseline: 9.8262x; 1.0557x over previous
#include <cuda_runtime.h>
#include <cuda_fp16.h>
#include <cstdint>

#define BB 16
#define TT 2048
#define DD 1024
#define HH 128
#define BT (BB*TT)

// ---------------- device scratch (allocation-free rule) ----------------
__device__ __align__(128) __half g_xh[(size_t)BT*DD];      // half copy of x
__device__ __align__(128) __half g_qh[(size_t)BT*HH];      // half, pre-scaled
__device__ __align__(128) __half g_kh[(size_t)BT*HH];
__device__ __align__(128) float  g_v [(size_t)BT*HH];      // fp32 (scaled later)
__device__ __align__(128) __half g_Wth[3*(size_t)HH*DD];   // [sel][n][k]
__device__ __align__(128) __half g_Vth[(size_t)BB*HH*TT];  // [b][h][k] = v/colsum
__device__ __align__(128) float  g_colsum[BT];
__device__ __align__(128) __half g_Eh[(size_t)BB*TT*TT];   // exp(masked S)

// ---------------- helpers ----------------
__device__ __forceinline__ uint32_t smem_u32(const void* p) {
    uint32_t a;
    asm("{ .reg .u64 t; cvta.to.shared.u64 t, %1; cvt.u32.u64 %0, t; }" : "=r"(a) : "l"(p));
    return a;
}
__device__ __forceinline__ void ldsm4(uint32_t& r0, uint32_t& r1, uint32_t& r2, uint32_t& r3,
                                      uint32_t addr) {
    asm volatile("ldmatrix.sync.aligned.m8n8.x4.shared.b16 {%0,%1,%2,%3}, [%4];"
                 : "=r"(r0), "=r"(r1), "=r"(r2), "=r"(r3) : "r"(addr));
}
__device__ __forceinline__ void mma16(float* c, const uint32_t* a, const uint32_t* b) {
    asm volatile(
        "mma.sync.aligned.m16n8k16.row.col.f32.f16.f16.f32 "
        "{%0,%1,%2,%3}, {%4,%5,%6,%7}, {%8,%9}, {%0,%1,%2,%3};"
        : "+f"(c[0]), "+f"(c[1]), "+f"(c[2]), "+f"(c[3])
        : "r"(a[0]), "r"(a[1]), "r"(a[2]), "r"(a[3]), "r"(b[0]), "r"(b[1]));
}

#define PH 40                    // halves per smem row (80B): ldmatrix conflict-free
#define TILEH (128*PH)           // halves per 128x32 tile
#define TILEB (TILEH*2)          // 10240 B
#define NSTAGE 3
#define GEMM_SMEM (NSTAGE*2*TILEB)   // 61440 B

// cp.async 16B stage of a 128x32-half chunk (row stride ld halves), 256 threads
__device__ __forceinline__ void stage_cp(uint32_t s, const __half* __restrict__ g,
                                         size_t ld, int tid) {
    #pragma unroll
    for (int i = 0; i < 2; i++) {
        int idx = tid + i * 256;
        int r = idx >> 2, c8 = idx & 3;
        uint32_t dst = s + (uint32_t)(r * PH + c8 * 8) * 2u;
        const __half* src = g + (size_t)r * ld + c8 * 8;
        asm volatile("cp.async.cg.shared.global [%0], [%1], 16;" :: "r"(dst), "l"(src));
    }
}
#define CP_COMMIT() asm volatile("cp.async.commit_group;" ::: "memory")

// warp tile 64(M) x 32(N): 8 warps as 2(M) x 4(N). One BK=32 slab = two k16 steps.
__device__ __forceinline__ void compute_tile(uint32_t sA, uint32_t sB,
                                             uint32_t aoff, uint32_t boff,
                                             float c[4][4][4]) {
    #pragma unroll
    for (int ks = 0; ks < 2; ks++) {
        uint32_t a[4][4], b[4][2];
        #pragma unroll
        for (int mt = 0; mt < 4; mt++)
            ldsm4(a[mt][0], a[mt][1], a[mt][2], a[mt][3],
                  sA + aoff + mt * (16 * PH * 2) + ks * 32);
        #pragma unroll
        for (int np = 0; np < 2; np++)
            ldsm4(b[2*np][0], b[2*np][1], b[2*np+1][0], b[2*np+1][1],
                  sB + boff + np * (16 * PH * 2) + ks * 32);
        #pragma unroll
        for (int mt = 0; mt < 4; mt++)
            #pragma unroll
            for (int nt = 0; nt < 4; nt++)
                mma16(c[mt][nt], a[mt], b[nt]);
    }
}

// block GEMM: C[128x128] = A[128xK] * B[128xK]^T, 256 threads, 3 cp.async stages
__device__ __forceinline__ void gemm_main(const __half* __restrict__ A, size_t lda,
                                          const __half* __restrict__ B, size_t ldb,
                                          int nkb, int tid, float c[4][4][4]) {
    extern __shared__ __half smh[];
    const uint32_t smb = smem_u32(smh);
    const int wid = tid >> 5, lane = tid & 31;
    const int wm = wid & 1, wn = wid >> 1;
    // ldmatrix lane offsets (bytes within tile)
    const uint32_t aoff = ((wm * 64 + (lane & 15)) * PH + (lane >> 4) * 8) * 2u;
    const uint32_t boff = ((wn * 32 + (lane & 7) + ((lane >> 4) << 3)) * PH
                           + ((lane >> 3) & 1) * 8) * 2u;

    stage_cp(smb,         A, lda, tid);
    stage_cp(smb + TILEB, B, ldb, tid);
    CP_COMMIT();
    if (nkb > 1) {
        stage_cp(smb + 2 * TILEB, A + 32, lda, tid);
        stage_cp(smb + 3 * TILEB, B + 32, ldb, tid);
    }
    CP_COMMIT();

    for (int kb = 0; kb < nkb; kb++) {
        asm volatile("cp.async.wait_group 1;" ::: "memory");
        __syncthreads();
        if (kb + 2 < nkb) {
            const int st = (kb + 2) % NSTAGE;
            stage_cp(smb + (2 * st) * TILEB,     A + (size_t)(kb + 2) * 32, lda, tid);
            stage_cp(smb + (2 * st + 1) * TILEB, B + (size_t)(kb + 2) * 32, ldb, tid);
        }
        CP_COMMIT();
        const int cs = kb % NSTAGE;
        compute_tile(smb + (2 * cs) * TILEB, smb + (2 * cs + 1) * TILEB, aoff, boff, c);
    }
}

#define ZERO_ACC(c) do { \
    _Pragma("unroll") for (int m = 0; m < 4; m++) \
    _Pragma("unroll") for (int n = 0; n < 4; n++) \
    _Pragma("unroll") for (int i = 0; i < 4; i++) (c)[m][n][i] = 0.f; } while (0)

// ---------------- prep kernels ----------------
__global__ void roundx_kernel(const float* __restrict__ x) {
    size_t i = ((size_t)blockIdx.x * blockDim.x + threadIdx.x) * 4;
    float4 f = *(const float4*)(x + i);
    *(__half2*)(g_xh + i)     = __floats2half2_rn(f.x, f.y);
    *(__half2*)(g_xh + i + 2) = __floats2half2_rn(f.z, f.w);
}

__global__ void zerocs_kernel() {
    int i = blockIdx.x * blockDim.x + threadIdx.x;
    if (i < BT) g_colsum[i] = 0.f;
}

__global__ void transW_kernel(const float* __restrict__ Wq, const float* __restrict__ Wk,
                              const float* __restrict__ Wv) {
    __shared__ float t[32][33];
    const int sel = blockIdx.z;
    const float* W = (sel == 0) ? Wq : (sel == 1) ? Wk : Wv;
    const int k0 = blockIdx.x * 32, n0 = blockIdx.y * 32;
    const int tx = threadIdx.x, ty = threadIdx.y;
    #pragma unroll
    for (int j = 0; j < 4; j++)
        t[ty + 8*j][tx] = W[(size_t)(k0 + ty + 8*j) * HH + n0 + tx];
    __syncthreads();
    #pragma unroll
    for (int j = 0; j < 4; j++)
        g_Wth[(size_t)sel * HH * DD + (size_t)(n0 + ty + 8*j) * DD + k0 + tx] =
            __float2half_rn(t[tx][ty + 8*j]);
}

__global__ void scaleV_kernel() {
    __shared__ float t[32][33];
    const int b = blockIdx.z;
    const int k0 = blockIdx.x * 32, h0 = blockIdx.y * 32;
    const int tx = threadIdx.x, ty = threadIdx.y;
    #pragma unroll
    for (int j = 0; j < 4; j++) {
        int kk = k0 + ty + 8*j;
        float inv = 1.0f / g_colsum[(size_t)b * TT + kk];
        t[ty + 8*j][tx] = g_v[((size_t)b * TT + kk) * HH + h0 + tx] * inv;
    }
    __syncthreads();
    #pragma unroll
    for (int j = 0; j < 4; j++)
        g_Vth[((size_t)b * HH + h0 + ty + 8*j) * TT + k0 + tx] =
            __float2half_rn(t[tx][ty + 8*j]);
}

// ---------------- GEMM kernels (256 threads, warp tile 64x32, fp16 mma) ----------------
__global__ __launch_bounds__(256, 2) void proj_tc(const float* __restrict__ bq,
                                                  const float* __restrict__ bk,
                                                  const float* __restrict__ bv) {
    const int tid = threadIdx.x;
    const int sel = blockIdx.y;
    const int row0 = blockIdx.x * 128;

    float c[4][4][4];
    ZERO_ACC(c);
    gemm_main(g_xh + (size_t)row0 * DD, DD,
              g_Wth + (size_t)sel * HH * DD, DD, DD / 32, tid, c);

    const int wid = tid >> 5, lane = tid & 31;
    const int wm = wid & 1, wn = wid >> 1;
    const int tr = lane >> 2, tc = lane & 3;
    const float* bias = (sel == 0) ? bq : (sel == 1) ? bk : bv;
    const float sc = (sel == 0) ? 0.08838834764831845f : 1.0f;

    #pragma unroll
    for (int mt = 0; mt < 4; mt++) {
        const int row = row0 + wm * 64 + mt * 16 + tr;
        #pragma unroll
        for (int nt = 0; nt < 4; nt++) {
            const int col = wn * 32 + nt * 8 + tc * 2;
            const float b0 = bias[col], b1 = bias[col + 1];
            float lx = (c[mt][nt][0] + b0) * sc;
            float ly = (c[mt][nt][1] + b1) * sc;
            float hx = (c[mt][nt][2] + b0) * sc;
            float hy = (c[mt][nt][3] + b1) * sc;
            if (sel != 2) {
                __half* dst = (sel == 0) ? g_qh : g_kh;
                *(__half2*)(dst + (size_t)row * HH + col)       = __floats2half2_rn(lx, ly);
                *(__half2*)(dst + (size_t)(row + 8) * HH + col) = __floats2half2_rn(hx, hy);
            } else {
                *(float2*)(g_v + (size_t)row * HH + col)       = make_float2(lx, ly);
                *(float2*)(g_v + (size_t)(row + 8) * HH + col) = make_float2(hx, hy);
            }
        }
    }
}

__global__ __launch_bounds__(256, 2) void scores_tc() {
    const int kt = blockIdx.x, qt = blockIdx.y, b = blockIdx.z;
    if (qt < kt) return;
    const int tid = threadIdx.x;
    const int q0 = qt * 128, k0 = kt * 128;

    float c[4][4][4];
    ZERO_ACC(c);
    gemm_main(g_qh + ((size_t)b * TT + q0) * HH, HH,
              g_kh + ((size_t)b * TT + k0) * HH, HH, HH / 32, tid, c);

    const int wid = tid >> 5, lane = tid & 31;
    const int wm = wid & 1, wn = wid >> 1;
    const int tr = lane >> 2, tc = lane & 3;

    __shared__ float red[128];
    __syncthreads();                 // all warps done with smem/GEMM
    if (tid < 128) red[tid] = 0.f;
    __syncthreads();

    #pragma unroll
    for (int nt = 0; nt < 4; nt++) {
        const int kcol = wn * 32 + nt * 8 + tc * 2;
        const int k = k0 + kcol;
        float cs0 = 0.f, cs1 = 0.f;
        #pragma unroll
        for (int mt = 0; mt < 4; mt++) {
            const int q = q0 + wm * 64 + mt * 16 + tr;
            float lx = (q     >= k    ) ? __expf(c[mt][nt][0]) : 0.f;
            float ly = (q     >= k + 1) ? __expf(c[mt][nt][1]) : 0.f;
            float hx = (q + 8 >= k    ) ? __expf(c[mt][nt][2]) : 0.f;
            float hy = (q + 8 >= k + 1) ? __expf(c[mt][nt][3]) : 0.f;
            *(__half2*)(g_Eh + ((size_t)b * TT + q) * TT + k)     = __floats2half2_rn(lx, ly);
            *(__half2*)(g_Eh + ((size_t)b * TT + q + 8) * TT + k) = __floats2half2_rn(hx, hy);
            cs0 += lx + hx;
            cs1 += ly + hy;
        }
        atomicAdd(&red[kcol],     cs0);
        atomicAdd(&red[kcol + 1], cs1);
    }
    __syncthreads();
    if (tid < 128) atomicAdd(&g_colsum[(size_t)b * TT + k0 + tid], red[tid]);
}

__global__ __launch_bounds__(256, 2) void pv_tc(float* __restrict__ out) {
    const int tid = threadIdx.x;
    const int qt = blockIdx.x, b = blockIdx.y;
    const int q0 = qt * 128;

    float c[4][4][4];
    ZERO_ACC(c);
    gemm_main(g_Eh + ((size_t)b * TT + q0) * TT, TT,
              g_Vth + (size_t)b * HH * TT, TT, (qt + 1) * 4, tid, c);

    const int wid = tid >> 5, lane = tid & 31;
    const int wm = wid & 1, wn = wid >> 1;
    const int tr = lane >> 2, tc = lane & 3;

    #pragma unroll
    for (int mt = 0; mt < 4; mt++) {
        const int q = q0 + wm * 64 + mt * 16 + tr;
        #pragma unroll
        for (int nt = 0; nt < 4; nt++) {
            const int col = wn * 32 + nt * 8 + tc * 2;
            *(float2*)(out + ((size_t)b * TT + q) * HH + col) =
                make_float2(c[mt][nt][0], c[mt][nt][1]);
            *(float2*)(out + ((size_t)b * TT + q + 8) * HH + col) =
                make_float2(c[mt][nt][2], c[mt][nt][3]);
        }
    }
}

// ---------------- launch ----------------
extern "C" void kernel_launch(void* const* d_in, const int* in_sizes, int n_in,
                              void* d_out, int out_size) {
    const float* x  = (const float*)d_in[0];
    const float* Wk = (const float*)d_in[1];
    const float* bk = (const float*)d_in[2];
    const float* Wq = (const float*)d_in[3];
    const float* bq = (const float*)d_in[4];
    const float* Wv = (const float*)d_in[5];
    const float* bv = (const float*)d_in[6];
    float* out = (float*)d_out;

    cudaFuncSetAttribute(proj_tc,   cudaFuncAttributeMaxDynamicSharedMemorySize, GEMM_SMEM);
    cudaFuncSetAttribute(scores_tc, cudaFuncAttributeMaxDynamicSharedMemorySize, GEMM_SMEM);
    cudaFuncSetAttribute(pv_tc,     cudaFuncAttributeMaxDynamicSharedMemorySize, GEMM_SMEM);

    roundx_kernel<<<(size_t)BT * DD / 1024, 256>>>(x);
    zerocs_kernel<<<(BT + 255) / 256, 256>>>();
    transW_kernel<<<dim3(DD/32, HH/32, 3), dim3(32, 8)>>>(Wq, Wk, Wv);
    proj_tc<<<dim3(BT/128, 3), 256, GEMM_SMEM>>>(bq, bk, bv);
    scores_tc<<<dim3(TT/128, TT/128, BB), 256, GEMM_SMEM>>>();
    scaleV_kernel<<<dim3(TT/32, HH/32, BB), dim3(32, 8)>>>();
    pv_tc<<<dim3(TT/128, BB), 256, GEMM_SMEM>>>(out);
}

// round 7
// speedup vs baseline: 10.9763x; 1.1170x over previous
#include <cuda_runtime.h>
#include <cuda_fp16.h>
#include <cstdint>

#define BB 16
#define TT 2048
#define DD 1024
#define HH 128
#define BT (BB*TT)

// ---------------- device scratch (allocation-free rule) ----------------
__device__ __align__(128) __half g_xh[(size_t)BT*DD];      // half copy of x
__device__ __align__(128) __half g_qh[(size_t)BT*HH];      // half, pre-scaled
__device__ __align__(128) __half g_kh[(size_t)BT*HH];
__device__ __align__(128) float  g_v [(size_t)BT*HH];      // fp32 (scaled later)
__device__ __align__(128) __half g_Wth[3*(size_t)HH*DD];   // [sel][n][k]
__device__ __align__(128) __half g_Vth[(size_t)BB*HH*TT];  // [b][h][k] = v/colsum
__device__ __align__(128) float  g_colsum[BT];
__device__ __align__(128) __half g_Eh[(size_t)BB*TT*TT];   // exp(masked S)

// ---------------- helpers ----------------
__device__ __forceinline__ uint32_t smem_u32(const void* p) {
    uint32_t a;
    asm("{ .reg .u64 t; cvta.to.shared.u64 t, %1; cvt.u32.u64 %0, t; }" : "=r"(a) : "l"(p));
    return a;
}
__device__ __forceinline__ void ldsm4(uint32_t& r0, uint32_t& r1, uint32_t& r2, uint32_t& r3,
                                      uint32_t addr) {
    asm volatile("ldmatrix.sync.aligned.m8n8.x4.shared.b16 {%0,%1,%2,%3}, [%4];"
                 : "=r"(r0), "=r"(r1), "=r"(r2), "=r"(r3) : "r"(addr));
}
__device__ __forceinline__ void mma16(float* c, const uint32_t* a, const uint32_t* b) {
    asm volatile(
        "mma.sync.aligned.m16n8k16.row.col.f32.f16.f16.f32 "
        "{%0,%1,%2,%3}, {%4,%5,%6,%7}, {%8,%9}, {%0,%1,%2,%3};"
        : "+f"(c[0]), "+f"(c[1]), "+f"(c[2]), "+f"(c[3])
        : "r"(a[0]), "r"(a[1]), "r"(a[2]), "r"(a[3]), "r"(b[0]), "r"(b[1]));
}

#define BK 64                    // k-slab (halves)
#define PH 72                    // halves per smem row (144B): ldmatrix conflict-free
#define TILEH (128*PH)
#define TILEB (TILEH*2)          // 18432 B per 128x64 tile
#define NSTAGE 3
#define GEMM_SMEM (NSTAGE*2*TILEB)   // 110592 B

// cp.async 16B stage of a 128x64-half chunk (row stride ld halves), 256 threads
__device__ __forceinline__ void stage_cp(uint32_t s, const __half* __restrict__ g,
                                         size_t ld, int tid) {
    #pragma unroll
    for (int i = 0; i < 4; i++) {
        int idx = tid + i * 256;
        int r = idx >> 3, c8 = idx & 7;
        uint32_t dst = s + (uint32_t)(r * PH + c8 * 8) * 2u;
        const __half* src = g + (size_t)r * ld + c8 * 8;
        asm volatile("cp.async.cg.shared.global [%0], [%1], 16;" :: "r"(dst), "l"(src));
    }
}
#define CP_COMMIT() asm volatile("cp.async.commit_group;" ::: "memory")

// warp tile 64(M) x 32(N): 8 warps as 2(M) x 4(N). One BK=64 slab = four k16 steps.
__device__ __forceinline__ void compute_tile(uint32_t sA, uint32_t sB,
                                             uint32_t aoff, uint32_t boff,
                                             float c[4][4][4]) {
    #pragma unroll
    for (int ks = 0; ks < 4; ks++) {
        uint32_t a[4][4], b[4][2];
        #pragma unroll
        for (int mt = 0; mt < 4; mt++)
            ldsm4(a[mt][0], a[mt][1], a[mt][2], a[mt][3],
                  sA + aoff + mt * (16 * PH * 2) + ks * 32);
        #pragma unroll
        for (int np = 0; np < 2; np++)
            ldsm4(b[2*np][0], b[2*np][1], b[2*np+1][0], b[2*np+1][1],
                  sB + boff + np * (16 * PH * 2) + ks * 32);
        #pragma unroll
        for (int mt = 0; mt < 4; mt++)
            #pragma unroll
            for (int nt = 0; nt < 4; nt++)
                mma16(c[mt][nt], a[mt], b[nt]);
    }
}

// block GEMM: C[128x128] = A[128xK] * B[128xK]^T, 256 threads, 3 cp.async stages
__device__ __forceinline__ void gemm_main(const __half* __restrict__ A, size_t lda,
                                          const __half* __restrict__ B, size_t ldb,
                                          int nkb, int tid, float c[4][4][4]) {
    extern __shared__ __half smh[];
    const uint32_t smb = smem_u32(smh);
    const int wid = tid >> 5, lane = tid & 31;
    const int wm = wid & 1, wn = wid >> 1;
    const uint32_t aoff = ((wm * 64 + (lane & 15)) * PH + (lane >> 4) * 8) * 2u;
    const uint32_t boff = ((wn * 32 + (lane & 7) + ((lane >> 4) << 3)) * PH
                           + ((lane >> 3) & 1) * 8) * 2u;

    __syncthreads();   // protect smem from previous GEMM in the same block

    stage_cp(smb,         A, lda, tid);
    stage_cp(smb + TILEB, B, ldb, tid);
    CP_COMMIT();
    if (nkb > 1) {
        stage_cp(smb + 2 * TILEB, A + BK, lda, tid);
        stage_cp(smb + 3 * TILEB, B + BK, ldb, tid);
    }
    CP_COMMIT();

    for (int kb = 0; kb < nkb; kb++) {
        asm volatile("cp.async.wait_group 1;" ::: "memory");
        __syncthreads();
        if (kb + 2 < nkb) {
            const int st = (kb + 2) % NSTAGE;
            stage_cp(smb + (2 * st) * TILEB,     A + (size_t)(kb + 2) * BK, lda, tid);
            stage_cp(smb + (2 * st + 1) * TILEB, B + (size_t)(kb + 2) * BK, ldb, tid);
        }
        CP_COMMIT();
        const int cs = kb % NSTAGE;
        compute_tile(smb + (2 * cs) * TILEB, smb + (2 * cs + 1) * TILEB, aoff, boff, c);
    }
}

#define ZERO_ACC(c) do { \
    _Pragma("unroll") for (int m = 0; m < 4; m++) \
    _Pragma("unroll") for (int n = 0; n < 4; n++) \
    _Pragma("unroll") for (int i = 0; i < 4; i++) (c)[m][n][i] = 0.f; } while (0)

// ---------------- prep kernels ----------------
__global__ void roundx_kernel(const float* __restrict__ x) {
    size_t i = ((size_t)blockIdx.x * blockDim.x + threadIdx.x) * 4;
    float4 f = *(const float4*)(x + i);
    *(__half2*)(g_xh + i)     = __floats2half2_rn(f.x, f.y);
    *(__half2*)(g_xh + i + 2) = __floats2half2_rn(f.z, f.w);
}

__global__ void zerocs_kernel() {
    int i = blockIdx.x * blockDim.x + threadIdx.x;
    if (i < BT) g_colsum[i] = 0.f;
}

__global__ void transW_kernel(const float* __restrict__ Wq, const float* __restrict__ Wk,
                              const float* __restrict__ Wv) {
    __shared__ float t[32][33];
    const int sel = blockIdx.z;
    const float* W = (sel == 0) ? Wq : (sel == 1) ? Wk : Wv;
    const int k0 = blockIdx.x * 32, n0 = blockIdx.y * 32;
    const int tx = threadIdx.x, ty = threadIdx.y;
    #pragma unroll
    for (int j = 0; j < 4; j++)
        t[ty + 8*j][tx] = W[(size_t)(k0 + ty + 8*j) * HH + n0 + tx];
    __syncthreads();
    #pragma unroll
    for (int j = 0; j < 4; j++)
        g_Wth[(size_t)sel * HH * DD + (size_t)(n0 + ty + 8*j) * DD + k0 + tx] =
            __float2half_rn(t[tx][ty + 8*j]);
}

__global__ void scaleV_kernel() {
    __shared__ float t[32][33];
    const int b = blockIdx.z;
    const int k0 = blockIdx.x * 32, h0 = blockIdx.y * 32;
    const int tx = threadIdx.x, ty = threadIdx.y;
    #pragma unroll
    for (int j = 0; j < 4; j++) {
        int kk = k0 + ty + 8*j;
        float inv = 1.0f / g_colsum[(size_t)b * TT + kk];
        t[ty + 8*j][tx] = g_v[((size_t)b * TT + kk) * HH + h0 + tx] * inv;
    }
    __syncthreads();
    #pragma unroll
    for (int j = 0; j < 4; j++)
        g_Vth[((size_t)b * HH + h0 + ty + 8*j) * TT + k0 + tx] =
            __float2half_rn(t[tx][ty + 8*j]);
}

// ---------------- GEMM kernels (256 threads, warp tile 64x32, fp16 mma) ----------------
__global__ __launch_bounds__(256, 2) void proj_tc(const float* __restrict__ bq,
                                                  const float* __restrict__ bk,
                                                  const float* __restrict__ bv) {
    const int tid = threadIdx.x;
    const int sel = blockIdx.y;
    const int row0 = blockIdx.x * 128;

    float c[4][4][4];
    ZERO_ACC(c);
    gemm_main(g_xh + (size_t)row0 * DD, DD,
              g_Wth + (size_t)sel * HH * DD, DD, DD / BK, tid, c);

    const int wid = tid >> 5, lane = tid & 31;
    const int wm = wid & 1, wn = wid >> 1;
    const int tr = lane >> 2, tc = lane & 3;
    const float* bias = (sel == 0) ? bq : (sel == 1) ? bk : bv;
    const float sc = (sel == 0) ? 0.08838834764831845f : 1.0f;

    #pragma unroll
    for (int mt = 0; mt < 4; mt++) {
        const int row = row0 + wm * 64 + mt * 16 + tr;
        #pragma unroll
        for (int nt = 0; nt < 4; nt++) {
            const int col = wn * 32 + nt * 8 + tc * 2;
            const float b0 = bias[col], b1 = bias[col + 1];
            float lx = (c[mt][nt][0] + b0) * sc;
            float ly = (c[mt][nt][1] + b1) * sc;
            float hx = (c[mt][nt][2] + b0) * sc;
            float hy = (c[mt][nt][3] + b1) * sc;
            if (sel != 2) {
                __half* dst = (sel == 0) ? g_qh : g_kh;
                *(__half2*)(dst + (size_t)row * HH + col)       = __floats2half2_rn(lx, ly);
                *(__half2*)(dst + (size_t)(row + 8) * HH + col) = __floats2half2_rn(hx, hy);
            } else {
                *(float2*)(g_v + (size_t)row * HH + col)       = make_float2(lx, ly);
                *(float2*)(g_v + (size_t)(row + 8) * HH + col) = make_float2(hx, hy);
            }
        }
    }
}

__global__ __launch_bounds__(256, 2) void scores_tc() {
    const int kt = blockIdx.x, qt = blockIdx.y, b = blockIdx.z;
    if (qt < kt) return;
    const int tid = threadIdx.x;
    const int q0 = qt * 128, k0 = kt * 128;

    float c[4][4][4];
    ZERO_ACC(c);
    gemm_main(g_qh + ((size_t)b * TT + q0) * HH, HH,
              g_kh + ((size_t)b * TT + k0) * HH, HH, HH / BK, tid, c);

    const int wid = tid >> 5, lane = tid & 31;
    const int wm = wid & 1, wn = wid >> 1;
    const int tr = lane >> 2, tc = lane & 3;

    __shared__ float red[128];
    __syncthreads();
    if (tid < 128) red[tid] = 0.f;
    __syncthreads();

    #pragma unroll
    for (int nt = 0; nt < 4; nt++) {
        const int kcol = wn * 32 + nt * 8 + tc * 2;
        const int k = k0 + kcol;
        float cs0 = 0.f, cs1 = 0.f;
        #pragma unroll
        for (int mt = 0; mt < 4; mt++) {
            const int q = q0 + wm * 64 + mt * 16 + tr;
            float lx = (q     >= k    ) ? __expf(c[mt][nt][0]) : 0.f;
            float ly = (q     >= k + 1) ? __expf(c[mt][nt][1]) : 0.f;
            float hx = (q + 8 >= k    ) ? __expf(c[mt][nt][2]) : 0.f;
            float hy = (q + 8 >= k + 1) ? __expf(c[mt][nt][3]) : 0.f;
            *(__half2*)(g_Eh + ((size_t)b * TT + q) * TT + k)     = __floats2half2_rn(lx, ly);
            *(__half2*)(g_Eh + ((size_t)b * TT + q + 8) * TT + k) = __floats2half2_rn(hx, hy);
            cs0 += lx + hx;
            cs1 += ly + hy;
        }
        atomicAdd(&red[kcol],     cs0);
        atomicAdd(&red[kcol + 1], cs1);
    }
    __syncthreads();
    if (tid < 128) atomicAdd(&g_colsum[(size_t)b * TT + k0 + tid], red[tid]);
}

// pv: block handles q-tiles (qtA = bx) and (qtB = 15-bx): 34 slabs per block, balanced
__global__ __launch_bounds__(256, 2) void pv_tc(float* __restrict__ out) {
    const int tid = threadIdx.x;
    const int b = blockIdx.y;
    const int wid = tid >> 5, lane = tid & 31;
    const int wm = wid & 1, wn = wid >> 1;
    const int tr = lane >> 2, tc = lane & 3;

    #pragma unroll
    for (int half = 0; half < 2; half++) {
        const int qt = half ? (TT/128 - 1 - blockIdx.x) : blockIdx.x;
        const int q0 = qt * 128;

        float c[4][4][4];
        ZERO_ACC(c);
        gemm_main(g_Eh + ((size_t)b * TT + q0) * TT, TT,
                  g_Vth + (size_t)b * HH * TT, TT, (qt + 1) * 2, tid, c);

        #pragma unroll
        for (int mt = 0; mt < 4; mt++) {
            const int q = q0 + wm * 64 + mt * 16 + tr;
            #pragma unroll
            for (int nt = 0; nt < 4; nt++) {
                const int col = wn * 32 + nt * 8 + tc * 2;
                *(float2*)(out + ((size_t)b * TT + q) * HH + col) =
                    make_float2(c[mt][nt][0], c[mt][nt][1]);
                *(float2*)(out + ((size_t)b * TT + q + 8) * HH + col) =
                    make_float2(c[mt][nt][2], c[mt][nt][3]);
            }
        }
    }
}

// ---------------- launch ----------------
extern "C" void kernel_launch(void* const* d_in, const int* in_sizes, int n_in,
                              void* d_out, int out_size) {
    const float* x  = (const float*)d_in[0];
    const float* Wk = (const float*)d_in[1];
    const float* bk = (const float*)d_in[2];
    const float* Wq = (const float*)d_in[3];
    const float* bq = (const float*)d_in[4];
    const float* Wv = (const float*)d_in[5];
    const float* bv = (const float*)d_in[6];
    float* out = (float*)d_out;

    cudaFuncSetAttribute(proj_tc,   cudaFuncAttributeMaxDynamicSharedMemorySize, GEMM_SMEM);
    cudaFuncSetAttribute(scores_tc, cudaFuncAttributeMaxDynamicSharedMemorySize, GEMM_SMEM);
    cudaFuncSetAttribute(pv_tc,     cudaFuncAttributeMaxDynamicSharedMemorySize, GEMM_SMEM);

    roundx_kernel<<<(size_t)BT * DD / 1024, 256>>>(x);
    zerocs_kernel<<<(BT + 255) / 256, 256>>>();
    transW_kernel<<<dim3(DD/32, HH/32, 3), dim3(32, 8)>>>(Wq, Wk, Wv);
    proj_tc<<<dim3(BT/128, 3), 256, GEMM_SMEM>>>(bq, bk, bv);
    scores_tc<<<dim3(TT/128, TT/128, BB), 256, GEMM_SMEM>>>();
    scaleV_kernel<<<dim3(TT/32, HH/32, BB), dim3(32, 8)>>>();
    pv_tc<<<dim3(TT/256, BB), 256, GEMM_SMEM>>>(out);
}